// round 1
// baseline (speedup 1.0000x reference)
#include <cuda_runtime.h>

#define NPTS 1024
#define NTHREADS 512

// gi = Wih @ gcn + bih, precomputed per (b,t) graph by the GCN kernel.
__device__ float g_gi[128 * 384];

__global__ void __launch_bounds__(512, 1) gcn_kernel(
    const float* __restrict__ points,
    const float* __restrict__ W1, const float* __restrict__ b1,
    const float* __restrict__ W2, const float* __restrict__ b2,
    const float* __restrict__ Wg, const float* __restrict__ bg,
    const float* __restrict__ Wih, const float* __restrict__ bih)
{
    extern __shared__ float sm[];
    float* px     = sm;                 // 1024
    float* py     = px + 1024;          // 1024
    float* dinv   = py + 1024;          // 1024
    float* sx     = dinv + 1024;        // 1024
    float* sy     = sx + 1024;          // 1024
    float* w1s    = sy + 1024;          // 128
    float* b1s    = w1s + 128;          // 64
    float* w2s    = b1s + 64;           // 4096
    float* b2s    = w2s + 4096;         // 64
    float* colsum = b2s + 64;           // 64
    float* wch    = colsum + 64;        // 1024*32 (offset 9536 floats -> 16B aligned)

    const int g   = blockIdx.x;      // graph = b*32 + t
    const int tid = threadIdx.x;
    const float thr2 = 0.3f * 0.3f;

    // ---- load points + weights into smem ----
    const float* pts = points + (size_t)g * NPTS * 2;
    for (int j = tid; j < NPTS; j += NTHREADS) {
        float2 p = ((const float2*)pts)[j];
        px[j] = p.x; py[j] = p.y;
    }
    for (int i = tid; i < 128; i += NTHREADS) w1s[i] = W1[i];
    for (int i = tid; i < 4096; i += NTHREADS) w2s[i] = W2[i];
    if (tid < 64) { b1s[tid] = b1[tid]; b2s[tid] = b2[tid]; colsum[tid] = 0.f; }
    __syncthreads();

    // ---- degree pass: deg[i] = #{j : dist(i,j) < 0.3} (includes self) ----
    for (int ig = 0; ig < 2; ig++) {
        int i = tid + ig * NTHREADS;
        float xi = px[i], yi = py[i];
        int cnt = 0;
        #pragma unroll 4
        for (int j = 0; j < NPTS; j++) {
            float dx = px[j] - xi;
            float dy = py[j] - yi;
            float d2 = fmaf(dx, dx, dy * dy);
            cnt += (d2 < thr2) ? 1 : 0;
        }
        dinv[i] = rsqrtf((float)cnt);
    }
    __syncthreads();

    // ---- s pass: s[i] = dinv_i * sum_j A_ij dinv_j pts[j]  (An @ pts) ----
    for (int ig = 0; ig < 2; ig++) {
        int i = tid + ig * NTHREADS;
        float xi = px[i], yi = py[i];
        float ax = 0.f, ay = 0.f;
        #pragma unroll 4
        for (int j = 0; j < NPTS; j++) {
            float dx = px[j] - xi;
            float dy = py[j] - yi;
            float d2 = fmaf(dx, dx, dy * dy);
            float m = (d2 < thr2) ? dinv[j] : 0.f;
            ax = fmaf(m, px[j], ax);
            ay = fmaf(m, py[j], ay);
        }
        float di = dinv[i];
        sx[i] = di * ax;
        sy[i] = di * ay;
    }
    __syncthreads();

    // ---- main: x2 = relu(An @ (diag(dinv)*x1 @ W2^T) + b2), colsum += x2 ----
    // w[j][m'] = dinv_j * sum_k relu(s_j . W1_k + b1_k) * W2[m'][k]
    // x2[i][m'] = relu(dinv_i * sum_j A_ij w[j][m'] + b2[m'])
    for (int c = 0; c < 2; c++) {
        // build 32-column chunk of w into smem
        for (int jj = tid; jj < NPTS; jj += NTHREADS) {
            float s0 = sx[jj], s1 = sy[jj];
            float x1r[64];
            #pragma unroll
            for (int k = 0; k < 64; k++) {
                float v = fmaf(s0, w1s[2*k], fmaf(s1, w1s[2*k+1], b1s[k]));
                x1r[k] = fmaxf(v, 0.f);
            }
            float dj = dinv[jj];
            #pragma unroll 1
            for (int m = 0; m < 32; m++) {
                const float* w2row = w2s + (c*32 + m) * 64;
                float acc2 = 0.f;
                #pragma unroll
                for (int k = 0; k < 64; k++)
                    acc2 = fmaf(x1r[k], w2row[k], acc2);
                wch[jj * 32 + m] = dj * acc2;
            }
        }
        __syncthreads();

        // sparse-sum over neighbors, dense FFMA2 with a in {0,1}
        for (int ig = 0; ig < 2; ig++) {
            int i = tid + ig * NTHREADS;
            float xi = px[i], yi = py[i];
            unsigned long long acc[16];
            #pragma unroll
            for (int q = 0; q < 16; q++) acc[q] = 0ULL;
            #pragma unroll 2
            for (int j = 0; j < NPTS; j++) {
                float dx = px[j] - xi;
                float dy = py[j] - yi;
                float d2 = fmaf(dx, dx, dy * dy);
                float a = (d2 < thr2) ? 1.0f : 0.0f;
                unsigned long long a2;
                asm("mov.b64 %0, {%1, %1};" : "=l"(a2) : "f"(a));
                const ulonglong2* wrow = (const ulonglong2*)(wch + j * 32);
                #pragma unroll
                for (int q = 0; q < 8; q++) {
                    ulonglong2 wv = wrow[q];
                    asm("fma.rn.f32x2 %0, %1, %2, %0;" : "+l"(acc[2*q])   : "l"(a2), "l"(wv.x));
                    asm("fma.rn.f32x2 %0, %1, %2, %0;" : "+l"(acc[2*q+1]) : "l"(a2), "l"(wv.y));
                }
            }
            float di = dinv[i];
            #pragma unroll
            for (int q = 0; q < 16; q++) {
                float lo, hi;
                asm("mov.b64 {%0, %1}, %2;" : "=f"(lo), "=f"(hi) : "l"(acc[q]));
                float v0 = fmaxf(fmaf(di, lo, b2s[c*32 + 2*q    ]), 0.f);
                float v1 = fmaxf(fmaf(di, hi, b2s[c*32 + 2*q + 1]), 0.f);
                #pragma unroll
                for (int off = 16; off > 0; off >>= 1) {
                    v0 += __shfl_xor_sync(0xffffffffu, v0, off);
                    v1 += __shfl_xor_sync(0xffffffffu, v1, off);
                }
                if ((tid & 31) == 0) {
                    atomicAdd(&colsum[c*32 + 2*q    ], v0);
                    atomicAdd(&colsum[c*32 + 2*q + 1], v1);
                }
            }
        }
        __syncthreads();
    }

    // ---- head: gcn = Wg @ mean + bg, then gi = Wih @ gcn + bih -> global ----
    if (tid < 64) {
        float acc = bg[tid];
        const float inv = 1.0f / 1024.f;
        #pragma unroll 8
        for (int m = 0; m < 64; m++)
            acc = fmaf(colsum[m] * inv, Wg[tid * 64 + m], acc);
        sx[tid] = acc;  // stage gcn vector (sx no longer needed)
    }
    __syncthreads();
    if (tid < 384) {
        float acc = bih[tid];
        const float* wr = Wih + tid * 64;
        #pragma unroll 8
        for (int c2 = 0; c2 < 64; c2++)
            acc = fmaf(wr[c2], sx[c2], acc);
        g_gi[g * 384 + tid] = acc;
    }
}

__global__ void __launch_bounds__(384, 1) gru_kernel(
    const float* __restrict__ Whh, const float* __restrict__ bhh,
    const float* __restrict__ Wf,  const float* __restrict__ bf,
    float* __restrict__ out)
{
    extern __shared__ float sm[];
    float* whh_s  = sm;                  // 384 * 129 (padded, conflict-free)
    float* h      = whh_s + 384 * 129;   // 128
    float* gh_s   = h + 128;             // 384
    float* gi_s   = gh_s + 384;          // 384
    float* hsum_s = gi_s + 384;          // 128

    const int b   = blockIdx.x;
    const int tid = threadIdx.x;

    for (int idx = tid; idx < 384 * 128; idx += 384) {
        int r = idx >> 7, c = idx & 127;
        whh_s[r * 129 + c] = Whh[idx];
    }
    if (tid < 128) { h[tid] = 0.f; hsum_s[tid] = 0.f; }
    __syncthreads();

    const float bhh_r = bhh[tid];
    for (int t = 0; t < 32; t++) {
        gi_s[tid] = g_gi[(b * 32 + t) * 384 + tid];
        // gh[r] = Whh[r] . h + bhh[r]
        float acc = bhh_r;
        const float* wr = whh_s + tid * 129;
        #pragma unroll 8
        for (int c = 0; c < 128; c++)
            acc = fmaf(wr[c], h[c], acc);
        gh_s[tid] = acc;
        __syncthreads();
        if (tid < 128) {
            float rg = 1.f / (1.f + __expf(-(gi_s[tid]       + gh_s[tid])));
            float zg = 1.f / (1.f + __expf(-(gi_s[128 + tid] + gh_s[128 + tid])));
            float ng = tanhf(gi_s[256 + tid] + rg * gh_s[256 + tid]);
            float hn = (1.f - zg) * ng + zg * h[tid];
            h[tid] = hn;
            hsum_s[tid] += hn;
        }
        __syncthreads();
    }
    // out[b][o] = Wf[o] . (hsum/32) + bf[o]
    if (tid < 2) {
        float acc = bf[tid];
        const float inv = 1.0f / 32.f;
        #pragma unroll 8
        for (int c = 0; c < 128; c++)
            acc = fmaf(Wf[tid * 128 + c], hsum_s[c] * inv, acc);
        out[b * 2 + tid] = acc;
    }
}

extern "C" void kernel_launch(void* const* d_in, const int* in_sizes, int n_in,
                              void* d_out, int out_size) {
    const float* points = (const float*)d_in[0];
    const float* W1  = (const float*)d_in[1];
    const float* b1  = (const float*)d_in[2];
    const float* W2  = (const float*)d_in[3];
    const float* b2  = (const float*)d_in[4];
    const float* Wg  = (const float*)d_in[5];
    const float* bg  = (const float*)d_in[6];
    const float* Wih = (const float*)d_in[7];
    const float* Whh = (const float*)d_in[8];
    const float* bih = (const float*)d_in[9];
    const float* bhh = (const float*)d_in[10];
    const float* Wf  = (const float*)d_in[11];
    const float* bf  = (const float*)d_in[12];
    float* out = (float*)d_out;

    const size_t smemA = (size_t)(1024*5 + 128 + 64 + 4096 + 64 + 64 + 1024*32) * sizeof(float);
    const size_t smemB = (size_t)(384*129 + 128 + 384 + 384 + 128) * sizeof(float);

    cudaFuncSetAttribute(gcn_kernel, cudaFuncAttributeMaxDynamicSharedMemorySize, (int)smemA);
    cudaFuncSetAttribute(gru_kernel, cudaFuncAttributeMaxDynamicSharedMemorySize, (int)smemB);

    gcn_kernel<<<128, NTHREADS, smemA>>>(points, W1, b1, W2, b2, Wg, bg, Wih, bih);
    gru_kernel<<<4, 384, smemB>>>(Whh, bhh, Wf, bf, out);
}

// round 2
// speedup vs baseline: 1.0032x; 1.0032x over previous
#include <cuda_runtime.h>

#define NPTS 1024
#define NTHREADS 512

// gi = Wih @ gcn + bih, precomputed per (b,t) graph by the GCN kernel.
__device__ float g_gi[128 * 384];

__global__ void __launch_bounds__(512, 1) gcn_kernel(
    const float* __restrict__ points,
    const float* __restrict__ W1, const float* __restrict__ b1,
    const float* __restrict__ W2, const float* __restrict__ b2,
    const float* __restrict__ Wg, const float* __restrict__ bg,
    const float* __restrict__ Wih, const float* __restrict__ bih)
{
    extern __shared__ float sm[];
    float* px     = sm;                 // 1024
    float* py     = px + 1024;          // 1024
    float* dinv   = py + 1024;          // 1024
    float* sx     = dinv + 1024;        // 1024
    float* sy     = sx + 1024;          // 1024
    float* w1s    = sy + 1024;          // 128
    float* b1s    = w1s + 128;          // 64
    float* w2s    = b1s + 64;           // 4096
    float* b2s    = w2s + 4096;         // 64
    float* colsum = b2s + 64;           // 64
    float* wch    = colsum + 64;        // 1024*32 (offset 9536 floats -> 16B aligned)

    const int g   = blockIdx.x;      // graph = b*32 + t
    const int tid = threadIdx.x;
    const float thr2 = 0.3f * 0.3f;

    // ---- load points + weights into smem ----
    const float* pts = points + (size_t)g * NPTS * 2;
    for (int j = tid; j < NPTS; j += NTHREADS) {
        float2 p = ((const float2*)pts)[j];
        px[j] = p.x; py[j] = p.y;
    }
    for (int i = tid; i < 128; i += NTHREADS) w1s[i] = W1[i];
    for (int i = tid; i < 4096; i += NTHREADS) w2s[i] = W2[i];
    if (tid < 64) { b1s[tid] = b1[tid]; b2s[tid] = b2[tid]; colsum[tid] = 0.f; }
    __syncthreads();

    // ---- degree pass: deg[i] = #{j : dist(i,j) < 0.3} (includes self) ----
    for (int ig = 0; ig < 2; ig++) {
        int i = tid + ig * NTHREADS;
        float xi = px[i], yi = py[i];
        int cnt = 0;
        #pragma unroll 4
        for (int j = 0; j < NPTS; j++) {
            float dx = px[j] - xi;
            float dy = py[j] - yi;
            float d2 = fmaf(dx, dx, dy * dy);
            cnt += (d2 < thr2) ? 1 : 0;
        }
        dinv[i] = rsqrtf((float)cnt);
    }
    __syncthreads();

    // ---- s pass: s[i] = dinv_i * sum_j A_ij dinv_j pts[j]  (An @ pts) ----
    for (int ig = 0; ig < 2; ig++) {
        int i = tid + ig * NTHREADS;
        float xi = px[i], yi = py[i];
        float ax = 0.f, ay = 0.f;
        #pragma unroll 4
        for (int j = 0; j < NPTS; j++) {
            float dx = px[j] - xi;
            float dy = py[j] - yi;
            float d2 = fmaf(dx, dx, dy * dy);
            float m = (d2 < thr2) ? dinv[j] : 0.f;
            ax = fmaf(m, px[j], ax);
            ay = fmaf(m, py[j], ay);
        }
        float di = dinv[i];
        sx[i] = di * ax;
        sy[i] = di * ay;
    }
    __syncthreads();

    // ---- main: x2 = relu(An @ (diag(dinv)*x1 @ W2^T) + b2), colsum += x2 ----
    // w[j][m'] = dinv_j * sum_k relu(s_j . W1_k + b1_k) * W2[m'][k]
    // x2[i][m'] = relu(dinv_i * sum_j A_ij w[j][m'] + b2[m'])
    for (int c = 0; c < 2; c++) {
        // build 32-column chunk of w into smem
        for (int jj = tid; jj < NPTS; jj += NTHREADS) {
            float s0 = sx[jj], s1 = sy[jj];
            float x1r[64];
            #pragma unroll
            for (int k = 0; k < 64; k++) {
                float v = fmaf(s0, w1s[2*k], fmaf(s1, w1s[2*k+1], b1s[k]));
                x1r[k] = fmaxf(v, 0.f);
            }
            float dj = dinv[jj];
            #pragma unroll 1
            for (int m = 0; m < 32; m++) {
                const float* w2row = w2s + (c*32 + m) * 64;
                float acc2 = 0.f;
                #pragma unroll
                for (int k = 0; k < 64; k++)
                    acc2 = fmaf(x1r[k], w2row[k], acc2);
                wch[jj * 32 + m] = dj * acc2;
            }
        }
        __syncthreads();

        // sparse-sum over neighbors, dense FFMA2 with a in {0,1}
        for (int ig = 0; ig < 2; ig++) {
            int i = tid + ig * NTHREADS;
            float xi = px[i], yi = py[i];
            unsigned long long acc[16];
            #pragma unroll
            for (int q = 0; q < 16; q++) acc[q] = 0ULL;
            #pragma unroll 2
            for (int j = 0; j < NPTS; j++) {
                float dx = px[j] - xi;
                float dy = py[j] - yi;
                float d2 = fmaf(dx, dx, dy * dy);
                float a = (d2 < thr2) ? 1.0f : 0.0f;
                unsigned long long a2;
                asm("mov.b64 %0, {%1, %1};" : "=l"(a2) : "f"(a));
                const ulonglong2* wrow = (const ulonglong2*)(wch + j * 32);
                #pragma unroll
                for (int q = 0; q < 8; q++) {
                    ulonglong2 wv = wrow[q];
                    asm("fma.rn.f32x2 %0, %1, %2, %0;" : "+l"(acc[2*q])   : "l"(a2), "l"(wv.x));
                    asm("fma.rn.f32x2 %0, %1, %2, %0;" : "+l"(acc[2*q+1]) : "l"(a2), "l"(wv.y));
                }
            }
            float di = dinv[i];
            #pragma unroll
            for (int q = 0; q < 16; q++) {
                float lo, hi;
                asm("mov.b64 {%0, %1}, %2;" : "=f"(lo), "=f"(hi) : "l"(acc[q]));
                float v0 = fmaxf(fmaf(di, lo, b2s[c*32 + 2*q    ]), 0.f);
                float v1 = fmaxf(fmaf(di, hi, b2s[c*32 + 2*q + 1]), 0.f);
                #pragma unroll
                for (int off = 16; off > 0; off >>= 1) {
                    v0 += __shfl_xor_sync(0xffffffffu, v0, off);
                    v1 += __shfl_xor_sync(0xffffffffu, v1, off);
                }
                if ((tid & 31) == 0) {
                    atomicAdd(&colsum[c*32 + 2*q    ], v0);
                    atomicAdd(&colsum[c*32 + 2*q + 1], v1);
                }
            }
        }
        __syncthreads();
    }

    // ---- head: gcn = Wg @ mean + bg, then gi = Wih @ gcn + bih -> global ----
    if (tid < 64) {
        float acc = bg[tid];
        const float inv = 1.0f / 1024.f;
        #pragma unroll 8
        for (int m = 0; m < 64; m++)
            acc = fmaf(colsum[m] * inv, Wg[tid * 64 + m], acc);
        sx[tid] = acc;  // stage gcn vector (sx no longer needed)
    }
    __syncthreads();
    if (tid < 384) {
        float acc = bih[tid];
        const float* wr = Wih + tid * 64;
        #pragma unroll 8
        for (int c2 = 0; c2 < 64; c2++)
            acc = fmaf(wr[c2], sx[c2], acc);
        g_gi[g * 384 + tid] = acc;
    }
}

__global__ void __launch_bounds__(384, 1) gru_kernel(
    const float* __restrict__ Whh, const float* __restrict__ bhh,
    const float* __restrict__ Wf,  const float* __restrict__ bf,
    float* __restrict__ out)
{
    extern __shared__ float sm[];
    float* whh_s  = sm;                  // 384 * 129 (padded, conflict-free)
    float* h      = whh_s + 384 * 129;   // 128
    float* gh_s   = h + 128;             // 384
    float* gi_s   = gh_s + 384;          // 384
    float* hsum_s = gi_s + 384;          // 128

    const int b   = blockIdx.x;
    const int tid = threadIdx.x;

    for (int idx = tid; idx < 384 * 128; idx += 384) {
        int r = idx >> 7, c = idx & 127;
        whh_s[r * 129 + c] = Whh[idx];
    }
    if (tid < 128) { h[tid] = 0.f; hsum_s[tid] = 0.f; }
    __syncthreads();

    const float bhh_r = bhh[tid];
    for (int t = 0; t < 32; t++) {
        gi_s[tid] = g_gi[(b * 32 + t) * 384 + tid];
        // gh[r] = Whh[r] . h + bhh[r]
        float acc = bhh_r;
        const float* wr = whh_s + tid * 129;
        #pragma unroll 8
        for (int c = 0; c < 128; c++)
            acc = fmaf(wr[c], h[c], acc);
        gh_s[tid] = acc;
        __syncthreads();
        if (tid < 128) {
            float rg = 1.f / (1.f + __expf(-(gi_s[tid]       + gh_s[tid])));
            float zg = 1.f / (1.f + __expf(-(gi_s[128 + tid] + gh_s[128 + tid])));
            float ng = tanhf(gi_s[256 + tid] + rg * gh_s[256 + tid]);
            float hn = (1.f - zg) * ng + zg * h[tid];
            h[tid] = hn;
            hsum_s[tid] += hn;
        }
        __syncthreads();
    }
    // out[b][o] = Wf[o] . (hsum/32) + bf[o]
    if (tid < 2) {
        float acc = bf[tid];
        const float inv = 1.0f / 32.f;
        #pragma unroll 8
        for (int c = 0; c < 128; c++)
            acc = fmaf(Wf[tid * 128 + c], hsum_s[c] * inv, acc);
        out[b * 2 + tid] = acc;
    }
}

extern "C" void kernel_launch(void* const* d_in, const int* in_sizes, int n_in,
                              void* d_out, int out_size) {
    const float* points = (const float*)d_in[0];
    const float* W1  = (const float*)d_in[1];
    const float* b1  = (const float*)d_in[2];
    const float* W2  = (const float*)d_in[3];
    const float* b2  = (const float*)d_in[4];
    const float* Wg  = (const float*)d_in[5];
    const float* bg  = (const float*)d_in[6];
    const float* Wih = (const float*)d_in[7];
    const float* Whh = (const float*)d_in[8];
    const float* bih = (const float*)d_in[9];
    const float* bhh = (const float*)d_in[10];
    const float* Wf  = (const float*)d_in[11];
    const float* bf  = (const float*)d_in[12];
    float* out = (float*)d_out;

    const size_t smemA = (size_t)(1024*5 + 128 + 64 + 4096 + 64 + 64 + 1024*32) * sizeof(float);
    const size_t smemB = (size_t)(384*129 + 128 + 384 + 384 + 128) * sizeof(float);

    cudaFuncSetAttribute(gcn_kernel, cudaFuncAttributeMaxDynamicSharedMemorySize, (int)smemA);
    cudaFuncSetAttribute(gru_kernel, cudaFuncAttributeMaxDynamicSharedMemorySize, (int)smemB);

    gcn_kernel<<<128, NTHREADS, smemA>>>(points, W1, b1, W2, b2, Wg, bg, Wih, bih);
    gru_kernel<<<4, 384, smemB>>>(Whh, bhh, Wf, bf, out);
}

// round 4
// speedup vs baseline: 2.4193x; 2.4117x over previous
#include <cuda_runtime.h>
#include <cuda_bf16.h>
#include <stdint.h>

#define NPTS 1024
#define NTH  512
#define THR2 0.09f

typedef unsigned long long u64;

// ---------------- smem byte-offset map (GCN kernel) ----------------
#define OFF_B    0        // 128KB: B fragments [k16(64)][nt(4)][lane(32)][16B: hi0,hi1,lo0,lo1]
#define OFF_PX   131072
#define OFF_PY   135168
#define OFF_DINV 139264
#define OFF_SX   143360
#define OFF_SY   147456
#define OFF_W2   151552   // 16KB
#define OFF_W1   167936   // 512B
#define OFF_B1   168448
#define OFF_B2   168704
#define OFF_CS   168960
#define OFF_GV   169216
#define SMEM_GCN 169472

__device__ float g_gi[128 * 384];

// ---------------- helpers ----------------
__device__ __forceinline__ u64 pack2f(float a, float b) {
    u64 r; asm("mov.b64 %0, {%1, %2};" : "=l"(r) : "f"(a), "f"(b)); return r;
}
__device__ __forceinline__ u64 ld2(const float* p) {
    float2 v = *(const float2*)p;
    return pack2f(v.x, v.y);
}
// mask pair: bf16x2 {adj(i,j0), adj(i,j1)} given packed point pair and packed -xi/-yi.
// u = (px-xi)^2 + (py-yi)^2 - thr2 ; neighbor <=> u < 0 (sign bit set; -0 ok, +0 => not)
__device__ __forceinline__ uint32_t maskpair(u64 px2, u64 py2, u64 nx2, u64 ny2,
                                             u64 one2, u64 nthr2) {
    u64 dx, dy, u;
    asm("fma.rn.f32x2 %0, %1, %2, %3;" : "=l"(dx) : "l"(px2), "l"(one2), "l"(nx2));
    asm("fma.rn.f32x2 %0, %1, %2, %3;" : "=l"(dy) : "l"(py2), "l"(one2), "l"(ny2));
    asm("fma.rn.f32x2 %0, %1, %1, %2;" : "=l"(u)  : "l"(dy), "l"(nthr2));
    asm("fma.rn.f32x2 %0, %1, %1, %0;" : "+l"(u)  : "l"(dx));
    uint32_t lo, hi, m;
    asm("mov.b64 {%0, %1}, %2;" : "=r"(lo), "=r"(hi) : "l"(u));
    asm("prmt.b32 %0, %1, %2, 0xFFBB;" : "=r"(m) : "r"(lo), "r"(hi));
    return m & 0x3F803F80u;   // bf16 1.0 per half where neighbor
}
__device__ __forceinline__ void mma_bf16(float* d, uint32_t a0, uint32_t a1,
                                         uint32_t a2, uint32_t a3,
                                         uint32_t b0, uint32_t b1) {
    asm("mma.sync.aligned.m16n8k16.row.col.f32.bf16.bf16.f32 "
        "{%0,%1,%2,%3}, {%4,%5,%6,%7}, {%8,%9}, {%0,%1,%2,%3};"
        : "+f"(d[0]), "+f"(d[1]), "+f"(d[2]), "+f"(d[3])
        : "r"(a0), "r"(a1), "r"(a2), "r"(a3), "r"(b0), "r"(b1));
}

// ---------------- GCN kernel ----------------
__global__ void __launch_bounds__(NTH, 1) gcn_kernel(
    const float* __restrict__ points,
    const float* __restrict__ W1, const float* __restrict__ b1,
    const float* __restrict__ W2, const float* __restrict__ b2,
    const float* __restrict__ Wg, const float* __restrict__ bg,
    const float* __restrict__ Wih, const float* __restrict__ bih)
{
    extern __shared__ char smem[];
    float* px   = (float*)(smem + OFF_PX);
    float* py   = (float*)(smem + OFF_PY);
    float* dinv = (float*)(smem + OFF_DINV);
    float* sx   = (float*)(smem + OFF_SX);
    float* sy   = (float*)(smem + OFF_SY);
    float* w2s  = (float*)(smem + OFF_W2);
    float* w1s  = (float*)(smem + OFF_W1);
    float* b1s  = (float*)(smem + OFF_B1);
    float* b2s  = (float*)(smem + OFF_B2);
    float* colsum = (float*)(smem + OFF_CS);
    float* gcnv   = (float*)(smem + OFF_GV);

    const int g    = blockIdx.x;
    const int tid  = threadIdx.x;
    const int lane = tid & 31;
    const int warp = tid >> 5;

    // ---- load points + weights ----
    const float* pts = points + (size_t)g * NPTS * 2;
    for (int j = tid; j < NPTS; j += NTH) {
        float2 p = ((const float2*)pts)[j];
        px[j] = p.x; py[j] = p.y;
    }
    for (int i = tid; i < 128; i += NTH)  w1s[i] = W1[i];
    for (int i = tid; i < 4096; i += NTH) w2s[i] = W2[i];
    if (tid < 64) { b1s[tid] = b1[tid]; b2s[tid] = b2[tid]; colsum[tid] = 0.f; }
    __syncthreads();

    // ---- degree pass ----
    for (int ig = 0; ig < 2; ig++) {
        int i = tid + ig * NTH;
        float xi = px[i], yi = py[i];
        int cnt = 0;
        #pragma unroll 4
        for (int j = 0; j < NPTS; j++) {
            float dx = px[j] - xi, dy = py[j] - yi;
            float d2 = fmaf(dx, dx, dy * dy);
            cnt += (d2 < THR2) ? 1 : 0;
        }
        dinv[i] = rsqrtf((float)cnt);
    }
    __syncthreads();

    // ---- s pass: s = An @ pts ----
    for (int ig = 0; ig < 2; ig++) {
        int i = tid + ig * NTH;
        float xi = px[i], yi = py[i];
        float ax = 0.f, ay = 0.f;
        #pragma unroll 4
        for (int j = 0; j < NPTS; j++) {
            float dx = px[j] - xi, dy = py[j] - yi;
            float d2 = fmaf(dx, dx, dy * dy);
            float m = (d2 < THR2) ? dinv[j] : 0.f;
            ax = fmaf(m, px[j], ax);
            ay = fmaf(m, py[j], ay);
        }
        float di = dinv[i];
        sx[i] = di * ax;
        sy[i] = di * ay;
    }
    __syncthreads();

    // =================== MMA phase (mma.sync HMMA, bf16 hi/lo) ===================
    const int R  = warp * 64;           // warp's 64 rows
    const int l4 = lane >> 2;
    const u64 one2  = pack2f(1.f, 1.f);
    const u64 nthr2 = pack2f(-THR2, -THR2);

    // -xi/-yi for the warp's 8 fragment rows (mt*2+half): i = R + mt*16 + l4 + half*8
    float nxr[8], nyr[8];
    #pragma unroll
    for (int q = 0; q < 8; q++) {
        int i = R + (q >> 1) * 16 + l4 + (q & 1) * 8;
        nxr[q] = -px[i]; nyr[q] = -py[i];
    }

    for (int c = 0; c < 2; c++) {
        __syncthreads();
        // ---- build B fragments (w hi/lo, cols c*32..c*32+31, all K) ----
        for (int jj = tid; jj < NPTS; jj += NTH) {
            float s0 = sx[jj], s1 = sy[jj], dj = dinv[jj];
            float x1r[64];
            #pragma unroll
            for (int k = 0; k < 64; k++) {
                float v = fmaf(s0, w1s[2*k], fmaf(s1, w1s[2*k+1], b1s[k]));
                x1r[k] = fmaxf(v, 0.f);
            }
            int k16 = jj >> 4, r = jj & 15;
            int bj = OFF_B + k16 * 2048 + ((r & 7) >> 1) * 16 + (r >> 3) * 4 + (r & 1) * 2;
            #pragma unroll 1
            for (int mm = 0; mm < 32; mm++) {
                const float* w2row = w2s + (c * 32 + mm) * 64;
                float acc = 0.f;
                #pragma unroll
                for (int k = 0; k < 64; k++) acc = fmaf(x1r[k], w2row[k], acc);
                float w = dj * acc;
                __nv_bfloat16 hb = __float2bfloat16(w);
                __nv_bfloat16 lb = __float2bfloat16(w - __bfloat162float(hb));
                int off = bj + (mm >> 3) * 512 + (mm & 7) * 64;
                *(__nv_bfloat16*)(smem + off)     = hb;
                *(__nv_bfloat16*)(smem + off + 8) = lb;
            }
        }
        __syncthreads();

        // ---- k-loop: A frags in registers, mma accumulate ----
        float acc[4][4][4] = {};
        #pragma unroll 1
        for (int k16 = 0; k16 < 64; k16++) {
            int jA = k16 * 16 + (lane & 3) * 2;
            u64 pax = ld2(px + jA),     pay = ld2(py + jA);
            u64 pbx = ld2(px + jA + 8), pby = ld2(py + jA + 8);

            uint32_t A[4][4];
            #pragma unroll
            for (int mt = 0; mt < 4; mt++) {
                u64 nx0 = pack2f(nxr[mt*2],   nxr[mt*2]);
                u64 ny0 = pack2f(nyr[mt*2],   nyr[mt*2]);
                u64 nx1 = pack2f(nxr[mt*2+1], nxr[mt*2+1]);
                u64 ny1 = pack2f(nyr[mt*2+1], nyr[mt*2+1]);
                A[mt][0] = maskpair(pax, pay, nx0, ny0, one2, nthr2); // (i0, jA pair)
                A[mt][1] = maskpair(pax, pay, nx1, ny1, one2, nthr2); // (i0+8, jA pair)
                A[mt][2] = maskpair(pbx, pby, nx0, ny0, one2, nthr2); // (i0, jB pair)
                A[mt][3] = maskpair(pbx, pby, nx1, ny1, one2, nthr2); // (i0+8, jB pair)
            }
            #pragma unroll
            for (int nt = 0; nt < 4; nt++) {
                uint4 bv = *(const uint4*)(smem + OFF_B + ((k16 * 4 + nt) * 32 + lane) * 16);
                #pragma unroll
                for (int mt = 0; mt < 4; mt++)
                    mma_bf16(acc[mt][nt], A[mt][0], A[mt][1], A[mt][2], A[mt][3], bv.x, bv.y);
                #pragma unroll
                for (int mt = 0; mt < 4; mt++)
                    mma_bf16(acc[mt][nt], A[mt][0], A[mt][1], A[mt][2], A[mt][3], bv.z, bv.w);
            }
        }

        // ---- epilogue: relu(dinv_i*acc + b2), column sums ----
        float cs[4][2] = {};
        #pragma unroll
        for (int mt = 0; mt < 4; mt++) {
            float di0 = dinv[R + mt*16 + l4];
            float di1 = dinv[R + mt*16 + l4 + 8];
            #pragma unroll
            for (int nt = 0; nt < 4; nt++) {
                int col0 = c * 32 + nt * 8 + (lane & 3) * 2;
                float b20 = b2s[col0], b21 = b2s[col0 + 1];
                cs[nt][0] += fmaxf(fmaf(di0, acc[mt][nt][0], b20), 0.f);
                cs[nt][1] += fmaxf(fmaf(di0, acc[mt][nt][1], b21), 0.f);
                cs[nt][0] += fmaxf(fmaf(di1, acc[mt][nt][2], b20), 0.f);
                cs[nt][1] += fmaxf(fmaf(di1, acc[mt][nt][3], b21), 0.f);
            }
        }
        #pragma unroll
        for (int nt = 0; nt < 4; nt++)
            #pragma unroll
            for (int p = 0; p < 2; p++) {
                float v = cs[nt][p];
                v += __shfl_xor_sync(0xffffffffu, v, 4);
                v += __shfl_xor_sync(0xffffffffu, v, 8);
                v += __shfl_xor_sync(0xffffffffu, v, 16);
                if (lane < 4)
                    atomicAdd(&colsum[c * 32 + nt * 8 + lane * 2 + p], v);
            }
    }
    __syncthreads();

    // ---- head: gcn = Wg @ mean + bg ; gi = Wih @ gcn + bih ----
    if (tid < 64) {
        float acc = bg[tid];
        const float inv = 1.0f / 1024.f;
        #pragma unroll 8
        for (int m = 0; m < 64; m++)
            acc = fmaf(colsum[m] * inv, Wg[tid * 64 + m], acc);
        gcnv[tid] = acc;
    }
    __syncthreads();
    if (tid < 384) {
        float acc = bih[tid];
        const float* wr = Wih + tid * 64;
        #pragma unroll 8
        for (int c2 = 0; c2 < 64; c2++)
            acc = fmaf(wr[c2], gcnv[c2], acc);
        g_gi[g * 384 + tid] = acc;
    }
}

// ---------------- GRU kernel ----------------
#define GOFF_WHH 0          // 64*384 float2 = 196608 B, layout [c2][r]
#define GOFF_H   196608     // 128 f32 (8B-aligned pairs)
#define GOFF_GH  197120     // 384 f32
#define SMEM_GRU 198656

__global__ void __launch_bounds__(384, 1) gru_kernel(
    const float* __restrict__ Whh, const float* __restrict__ bhh,
    const float* __restrict__ Wf,  const float* __restrict__ bf,
    float* __restrict__ out)
{
    extern __shared__ char smg[];
    float2* whh2 = (float2*)(smg + GOFF_WHH);
    float*  h    = (float*)(smg + GOFF_H);
    float*  gh_s = (float*)(smg + GOFF_GH);
    const u64* whhu = (const u64*)(smg + GOFF_WHH);
    const u64* hu   = (const u64*)(smg + GOFF_H);

    const int b   = blockIdx.x;
    const int tid = threadIdx.x;

    const float2* whg = (const float2*)Whh;     // Whh[r][c], pairs over c
    for (int c2 = 0; c2 < 64; c2++)
        whh2[c2 * 384 + tid] = whg[tid * 64 + c2];
    if (tid < 128) h[tid] = 0.f;
    __syncthreads();

    const float bhh_r = bhh[tid];
    float hsum = 0.f;
    const float* gib = g_gi + (size_t)b * 32 * 384;

    for (int t = 0; t < 32; t++) {
        // gh[r] = Whh[r] . h + bhh[r] via packed f32x2
        u64 acc2 = pack2f(bhh_r, 0.f);
        #pragma unroll 8
        for (int c2 = 0; c2 < 64; c2++) {
            u64 wv = whhu[c2 * 384 + tid];
            u64 h2 = hu[c2];
            asm("fma.rn.f32x2 %0, %1, %2, %0;" : "+l"(acc2) : "l"(wv), "l"(h2));
        }
        float alo, ahi;
        asm("mov.b64 {%0, %1}, %2;" : "=f"(alo), "=f"(ahi) : "l"(acc2));
        gh_s[tid] = alo + ahi;
        __syncthreads();

        if (tid < 128) {
            const float* git = gib + t * 384;
            float rg = 1.f / (1.f + __expf(-(git[tid]       + gh_s[tid])));
            float zg = 1.f / (1.f + __expf(-(git[128 + tid] + gh_s[128 + tid])));
            float ng = tanhf(git[256 + tid] + rg * gh_s[256 + tid]);
            float hn = (1.f - zg) * ng + zg * h[tid];
            h[tid] = hn;
            hsum += hn;
        }
        __syncthreads();
    }

    if (tid < 128) gh_s[tid] = hsum;   // reuse gh_s as hsum staging
    __syncthreads();
    if (tid < 2) {
        float acc = bf[tid];
        const float inv = 1.0f / 32.f;
        #pragma unroll 8
        for (int c = 0; c < 128; c++)
            acc = fmaf(Wf[tid * 128 + c], gh_s[c] * inv, acc);
        out[b * 2 + tid] = acc;
    }
}

extern "C" void kernel_launch(void* const* d_in, const int* in_sizes, int n_in,
                              void* d_out, int out_size) {
    const float* points = (const float*)d_in[0];
    const float* W1  = (const float*)d_in[1];
    const float* b1  = (const float*)d_in[2];
    const float* W2  = (const float*)d_in[3];
    const float* b2  = (const float*)d_in[4];
    const float* Wg  = (const float*)d_in[5];
    const float* bg  = (const float*)d_in[6];
    const float* Wih = (const float*)d_in[7];
    const float* Whh = (const float*)d_in[8];
    const float* bih = (const float*)d_in[9];
    const float* bhh = (const float*)d_in[10];
    const float* Wf  = (const float*)d_in[11];
    const float* bf  = (const float*)d_in[12];
    float* out = (float*)d_out;

    cudaFuncSetAttribute(gcn_kernel, cudaFuncAttributeMaxDynamicSharedMemorySize, SMEM_GCN);
    cudaFuncSetAttribute(gru_kernel, cudaFuncAttributeMaxDynamicSharedMemorySize, SMEM_GRU);

    gcn_kernel<<<128, NTH, SMEM_GCN>>>(points, W1, b1, W2, b2, Wg, bg, Wih, bih);
    gru_kernel<<<4, 384, SMEM_GRU>>>(Whh, bhh, Wf, bf, out);
}

// round 5
// speedup vs baseline: 3.1063x; 1.2840x over previous
#include <cuda_runtime.h>
#include <cuda_bf16.h>
#include <stdint.h>

#define NPTS 1024
#define NTH  512
#define THR2 0.09f

typedef unsigned long long u64;

// ---------------- smem byte-offset map (GCN kernel) ----------------
#define OFF_B    0        // 128KB: B fragments [k16(64)][nt(4)][lane(32)][16B: hi0,hi1,lo0,lo1]
#define OFF_PX   131072
#define OFF_PY   135168
#define OFF_DINV 139264
#define OFF_SX   143360
#define OFF_SY   147456
#define OFF_W2   151552   // 16KB
#define OFF_W1   167936   // 512B
#define OFF_B1   168448
#define OFF_B2   168704
#define OFF_CS   168960
#define OFF_GV   169216
#define SMEM_GCN 169472

__device__ float g_gi[128 * 384];

// ---------------- helpers ----------------
__device__ __forceinline__ u64 pack2f(float a, float b) {
    u64 r; asm("mov.b64 %0, {%1, %2};" : "=l"(r) : "f"(a), "f"(b)); return r;
}
__device__ __forceinline__ u64 ld2(const float* p) {
    float2 v = *(const float2*)p;
    return pack2f(v.x, v.y);
}
#define FMA2(acc, a, b) asm("fma.rn.f32x2 %0, %1, %2, %0;" : "+l"(acc) : "l"(a), "l"(b))
__device__ __forceinline__ u64 add2(u64 a, u64 b) {
    u64 r; asm("add.rn.f32x2 %0, %1, %2;" : "=l"(r) : "l"(a), "l"(b)); return r;
}
__device__ __forceinline__ u64 fma2v(u64 a, u64 b, u64 c) {
    u64 r; asm("fma.rn.f32x2 %0, %1, %2, %3;" : "=l"(r) : "l"(a), "l"(b), "l"(c)); return r;
}
// mask pair: bf16x2 {adj(i,j0), adj(i,j1)}; u = dx^2 + dy^2 - thr2, neighbor <=> sign(u)
__device__ __forceinline__ uint32_t maskpair(u64 px2, u64 py2, u64 nx2, u64 ny2,
                                             u64 one2, u64 nthr2) {
    u64 dx, dy, u;
    asm("fma.rn.f32x2 %0, %1, %2, %3;" : "=l"(dx) : "l"(px2), "l"(one2), "l"(nx2));
    asm("fma.rn.f32x2 %0, %1, %2, %3;" : "=l"(dy) : "l"(py2), "l"(one2), "l"(ny2));
    asm("fma.rn.f32x2 %0, %1, %1, %2;" : "=l"(u)  : "l"(dy), "l"(nthr2));
    asm("fma.rn.f32x2 %0, %1, %1, %0;" : "+l"(u)  : "l"(dx));
    uint32_t lo, hi, m;
    asm("mov.b64 {%0, %1}, %2;" : "=r"(lo), "=r"(hi) : "l"(u));
    asm("prmt.b32 %0, %1, %2, 0xFFBB;" : "=r"(m) : "r"(lo), "r"(hi));
    return m & 0x3F803F80u;
}
__device__ __forceinline__ void mma_bf16(float* d, uint32_t a0, uint32_t a1,
                                         uint32_t a2, uint32_t a3,
                                         uint32_t b0, uint32_t b1) {
    asm("mma.sync.aligned.m16n8k16.row.col.f32.bf16.bf16.f32 "
        "{%0,%1,%2,%3}, {%4,%5,%6,%7}, {%8,%9}, {%0,%1,%2,%3};"
        : "+f"(d[0]), "+f"(d[1]), "+f"(d[2]), "+f"(d[3])
        : "r"(a0), "r"(a1), "r"(a2), "r"(a3), "r"(b0), "r"(b1));
}

// ---------------- GCN kernel ----------------
__global__ void __launch_bounds__(NTH, 1) gcn_kernel(
    const float* __restrict__ points,
    const float* __restrict__ W1, const float* __restrict__ b1,
    const float* __restrict__ W2, const float* __restrict__ b2,
    const float* __restrict__ Wg, const float* __restrict__ bg,
    const float* __restrict__ Wih, const float* __restrict__ bih)
{
    extern __shared__ char smem[];
    float* px   = (float*)(smem + OFF_PX);
    float* py   = (float*)(smem + OFF_PY);
    float* dinv = (float*)(smem + OFF_DINV);
    float* sx   = (float*)(smem + OFF_SX);
    float* sy   = (float*)(smem + OFF_SY);
    float* w2s  = (float*)(smem + OFF_W2);
    float* w1s  = (float*)(smem + OFF_W1);
    float* b1s  = (float*)(smem + OFF_B1);
    float* b2s  = (float*)(smem + OFF_B2);
    float* colsum = (float*)(smem + OFF_CS);
    float* gcnv   = (float*)(smem + OFF_GV);

    const int g    = blockIdx.x;
    const int tid  = threadIdx.x;
    const int lane = tid & 31;
    const int warp = tid >> 5;

    // ---- load points + weights ----
    const float* pts = points + (size_t)g * NPTS * 2;
    for (int j = tid; j < NPTS; j += NTH) {
        float2 p = ((const float2*)pts)[j];
        px[j] = p.x; py[j] = p.y;
    }
    for (int i = tid; i < 128; i += NTH)  w1s[i] = W1[i];
    for (int i = tid; i < 4096; i += NTH) w2s[i] = W2[i];
    if (tid < 64) { b1s[tid] = b1[tid]; b2s[tid] = b2[tid]; colsum[tid] = 0.f; }
    __syncthreads();

    const u64 one2  = pack2f(1.f, 1.f);
    const u64 nthr2 = pack2f(-THR2, -THR2);
    const u64* pxp = (const u64*)px;
    const u64* pyp = (const u64*)py;

    // ---- degree pass (packed f32x2, sign-bit count) ----
    for (int ig = 0; ig < 2; ig++) {
        int i = tid + ig * NTH;
        u64 nxi = pack2f(-px[i], -px[i]);
        u64 nyi = pack2f(-py[i], -py[i]);
        uint32_t cnt = 0;
        #pragma unroll 4
        for (int jp = 0; jp < NPTS / 2; jp++) {
            u64 dx2 = add2(pxp[jp], nxi);
            u64 dy2 = add2(pyp[jp], nyi);
            u64 u = fma2v(dy2, dy2, nthr2);
            FMA2(u, dx2, dx2);
            cnt += ((uint32_t)u >> 31) + ((uint32_t)(u >> 32) >> 31);
        }
        dinv[i] = rsqrtf((float)cnt);
    }
    __syncthreads();

    // ---- s pass: s = An @ pts (packed f32x2, sign-mask select of dinv) ----
    const u64* dvp = (const u64*)dinv;
    for (int ig = 0; ig < 2; ig++) {
        int i = tid + ig * NTH;
        u64 nxi = pack2f(-px[i], -px[i]);
        u64 nyi = pack2f(-py[i], -py[i]);
        u64 ax2 = 0ULL, ay2 = 0ULL;
        #pragma unroll 4
        for (int jp = 0; jp < NPTS / 2; jp++) {
            u64 px2 = pxp[jp], py2 = pyp[jp];
            u64 dx2 = add2(px2, nxi);
            u64 dy2 = add2(py2, nyi);
            u64 u = fma2v(dy2, dy2, nthr2);
            FMA2(u, dx2, dx2);
            uint32_t mlo = (uint32_t)(((int32_t)(uint32_t)u) >> 31);
            uint32_t mhi = (uint32_t)(((int32_t)(uint32_t)(u >> 32)) >> 31);
            u64 dv = dvp[jp];
            u64 m2 = (u64)((uint32_t)dv & mlo) | (((u64)((uint32_t)(dv >> 32) & mhi)) << 32);
            FMA2(ax2, m2, px2);
            FMA2(ay2, m2, py2);
        }
        float axl, axh, ayl, ayh;
        asm("mov.b64 {%0, %1}, %2;" : "=f"(axl), "=f"(axh) : "l"(ax2));
        asm("mov.b64 {%0, %1}, %2;" : "=f"(ayl), "=f"(ayh) : "l"(ay2));
        float di = dinv[i];
        sx[i] = di * (axl + axh);
        sy[i] = di * (ayl + ayh);
    }
    __syncthreads();

    // =================== MMA phase (mma.sync HMMA, bf16 hi/lo) ===================
    const int R  = warp * 64;
    const int l4 = lane >> 2;

    float nxr[8], nyr[8];
    #pragma unroll
    for (int q = 0; q < 8; q++) {
        int i = R + (q >> 1) * 16 + l4 + (q & 1) * 8;
        nxr[q] = -px[i]; nyr[q] = -py[i];
    }

    for (int c = 0; c < 2; c++) {
        __syncthreads();
        // ---- build B fragments (w hi/lo, cols c*32..c*32+31, all K), f32x2 dots ----
        for (int jj = tid; jj < NPTS; jj += NTH) {
            float s0 = sx[jj], s1 = sy[jj], dj = dinv[jj];
            u64 x1p[32];
            #pragma unroll
            for (int k2 = 0; k2 < 32; k2++) {
                float v0 = fmaxf(fmaf(s0, w1s[4*k2],   fmaf(s1, w1s[4*k2+1], b1s[2*k2])),   0.f) * dj;
                float v1 = fmaxf(fmaf(s0, w1s[4*k2+2], fmaf(s1, w1s[4*k2+3], b1s[2*k2+1])), 0.f) * dj;
                x1p[k2] = pack2f(v0, v1);
            }
            int k16 = jj >> 4, r = jj & 15;
            int bj = OFF_B + k16 * 2048 + ((r & 7) >> 1) * 16 + (r >> 3) * 4 + (r & 1) * 2;
            #pragma unroll 1
            for (int mm = 0; mm < 32; mm++) {
                const u64* w2p = (const u64*)(w2s + (c * 32 + mm) * 64);
                u64 a2 = 0ULL;
                #pragma unroll
                for (int k2 = 0; k2 < 32; k2++) FMA2(a2, x1p[k2], w2p[k2]);
                float al, ah;
                asm("mov.b64 {%0, %1}, %2;" : "=f"(al), "=f"(ah) : "l"(a2));
                float w = al + ah;
                __nv_bfloat16 hb = __float2bfloat16(w);
                __nv_bfloat16 lb = __float2bfloat16(w - __bfloat162float(hb));
                int off = bj + (mm >> 3) * 512 + (mm & 7) * 64;
                *(__nv_bfloat16*)(smem + off)     = hb;
                *(__nv_bfloat16*)(smem + off + 8) = lb;
            }
        }
        __syncthreads();

        // ---- k-loop: A frags in registers, mma accumulate ----
        float acc[4][4][4] = {};
        #pragma unroll 1
        for (int k16 = 0; k16 < 64; k16++) {
            int jA = k16 * 16 + (lane & 3) * 2;
            u64 pax = ld2(px + jA),     pay = ld2(py + jA);
            u64 pbx = ld2(px + jA + 8), pby = ld2(py + jA + 8);

            uint32_t A[4][4];
            #pragma unroll
            for (int mt = 0; mt < 4; mt++) {
                u64 nx0 = pack2f(nxr[mt*2],   nxr[mt*2]);
                u64 ny0 = pack2f(nyr[mt*2],   nyr[mt*2]);
                u64 nx1 = pack2f(nxr[mt*2+1], nxr[mt*2+1]);
                u64 ny1 = pack2f(nyr[mt*2+1], nyr[mt*2+1]);
                A[mt][0] = maskpair(pax, pay, nx0, ny0, one2, nthr2);
                A[mt][1] = maskpair(pax, pay, nx1, ny1, one2, nthr2);
                A[mt][2] = maskpair(pbx, pby, nx0, ny0, one2, nthr2);
                A[mt][3] = maskpair(pbx, pby, nx1, ny1, one2, nthr2);
            }
            #pragma unroll
            for (int nt = 0; nt < 4; nt++) {
                uint4 bv = *(const uint4*)(smem + OFF_B + ((k16 * 4 + nt) * 32 + lane) * 16);
                #pragma unroll
                for (int mt = 0; mt < 4; mt++)
                    mma_bf16(acc[mt][nt], A[mt][0], A[mt][1], A[mt][2], A[mt][3], bv.x, bv.y);
                #pragma unroll
                for (int mt = 0; mt < 4; mt++)
                    mma_bf16(acc[mt][nt], A[mt][0], A[mt][1], A[mt][2], A[mt][3], bv.z, bv.w);
            }
        }

        // ---- epilogue: relu(dinv_i*acc + b2), column sums ----
        float cs[4][2] = {};
        #pragma unroll
        for (int mt = 0; mt < 4; mt++) {
            float di0 = dinv[R + mt*16 + l4];
            float di1 = dinv[R + mt*16 + l4 + 8];
            #pragma unroll
            for (int nt = 0; nt < 4; nt++) {
                int col0 = c * 32 + nt * 8 + (lane & 3) * 2;
                float b20 = b2s[col0], b21 = b2s[col0 + 1];
                cs[nt][0] += fmaxf(fmaf(di0, acc[mt][nt][0], b20), 0.f);
                cs[nt][1] += fmaxf(fmaf(di0, acc[mt][nt][1], b21), 0.f);
                cs[nt][0] += fmaxf(fmaf(di1, acc[mt][nt][2], b20), 0.f);
                cs[nt][1] += fmaxf(fmaf(di1, acc[mt][nt][3], b21), 0.f);
            }
        }
        #pragma unroll
        for (int nt = 0; nt < 4; nt++)
            #pragma unroll
            for (int p = 0; p < 2; p++) {
                float v = cs[nt][p];
                v += __shfl_xor_sync(0xffffffffu, v, 4);
                v += __shfl_xor_sync(0xffffffffu, v, 8);
                v += __shfl_xor_sync(0xffffffffu, v, 16);
                if (lane < 4)
                    atomicAdd(&colsum[c * 32 + nt * 8 + lane * 2 + p], v);
            }
    }
    __syncthreads();

    // ---- head: gcn = Wg @ mean + bg ; gi = Wih @ gcn + bih ----
    if (tid < 64) {
        float acc = bg[tid];
        const float inv = 1.0f / 1024.f;
        #pragma unroll 8
        for (int m = 0; m < 64; m++)
            acc = fmaf(colsum[m] * inv, Wg[tid * 64 + m], acc);
        gcnv[tid] = acc;
    }
    __syncthreads();
    if (tid < 384) {
        float acc = bih[tid];
        const float* wr = Wih + tid * 64;
        #pragma unroll 8
        for (int c2 = 0; c2 < 64; c2++)
            acc = fmaf(wr[c2], gcnv[c2], acc);
        g_gi[g * 384 + tid] = acc;
    }
}

// ---------------- GRU kernel: Whh resident in registers ----------------
__global__ void __launch_bounds__(384, 1) gru_kernel(
    const float* __restrict__ Whh, const float* __restrict__ bhh,
    const float* __restrict__ Wf,  const float* __restrict__ bf,
    float* __restrict__ out)
{
    __shared__ __align__(16) float h[128];
    __shared__ float gh_s[384];
    __shared__ float gi_s[384];
    __shared__ float hsum_s[128];

    const int b   = blockIdx.x;
    const int tid = threadIdx.x;

    // thread tid owns row tid of Whh: 128 weights as 64 packed f32x2 registers
    u64 wreg[64];
    const u64* wg = (const u64*)Whh;
    #pragma unroll
    for (int c2 = 0; c2 < 64; c2++) wreg[c2] = wg[tid * 64 + c2];

    if (tid < 128) h[tid] = 0.f;
    const float bhh_r = bhh[tid];
    const float* gib = g_gi + (size_t)b * 32 * 384;
    float gi_cur = gib[tid];
    float hsum = 0.f;
    __syncthreads();

    for (int t = 0; t < 32; t++) {
        float gi_nxt = (t < 31) ? gib[(t + 1) * 384 + tid] : 0.f;
        gi_s[tid] = gi_cur;

        // gh[tid] = Whh[tid] . h + bhh[tid], packed f32x2, h via 128-bit loads
        u64 acc2 = pack2f(bhh_r, 0.f);
        const double2* hv4 = (const double2*)h;
        #pragma unroll
        for (int c4 = 0; c4 < 32; c4++) {
            double2 hv = hv4[c4];
            u64 h0 = __double_as_longlong(hv.x);
            u64 h1 = __double_as_longlong(hv.y);
            FMA2(acc2, wreg[2*c4],     h0);
            FMA2(acc2, wreg[2*c4 + 1], h1);
        }
        float alo, ahi;
        asm("mov.b64 {%0, %1}, %2;" : "=f"(alo), "=f"(ahi) : "l"(acc2));
        gh_s[tid] = alo + ahi;
        __syncthreads();

        if (tid < 128) {
            float rg = 1.f / (1.f + __expf(-(gi_s[tid]       + gh_s[tid])));
            float zg = 1.f / (1.f + __expf(-(gi_s[128 + tid] + gh_s[128 + tid])));
            float ng = tanhf(gi_s[256 + tid] + rg * gh_s[256 + tid]);
            float hn = (1.f - zg) * ng + zg * h[tid];
            h[tid] = hn;
            hsum += hn;
        }
        __syncthreads();
        gi_cur = gi_nxt;
    }

    if (tid < 128) hsum_s[tid] = hsum;
    __syncthreads();
    if (tid < 2) {
        float acc = bf[tid];
        const float inv = 1.0f / 32.f;
        #pragma unroll 8
        for (int c = 0; c < 128; c++)
            acc = fmaf(Wf[tid * 128 + c], hsum_s[c] * inv, acc);
        out[b * 2 + tid] = acc;
    }
}

extern "C" void kernel_launch(void* const* d_in, const int* in_sizes, int n_in,
                              void* d_out, int out_size) {
    const float* points = (const float*)d_in[0];
    const float* W1  = (const float*)d_in[1];
    const float* b1  = (const float*)d_in[2];
    const float* W2  = (const float*)d_in[3];
    const float* b2  = (const float*)d_in[4];
    const float* Wg  = (const float*)d_in[5];
    const float* bg  = (const float*)d_in[6];
    const float* Wih = (const float*)d_in[7];
    const float* Whh = (const float*)d_in[8];
    const float* bih = (const float*)d_in[9];
    const float* bhh = (const float*)d_in[10];
    const float* Wf  = (const float*)d_in[11];
    const float* bf  = (const float*)d_in[12];
    float* out = (float*)d_out;

    cudaFuncSetAttribute(gcn_kernel, cudaFuncAttributeMaxDynamicSharedMemorySize, SMEM_GCN);

    gcn_kernel<<<128, NTH, SMEM_GCN>>>(points, W1, b1, W2, b2, Wg, bg, Wih, bih);
    gru_kernel<<<4, 384>>>(Whh, bhh, Wf, bf, out);
}

// round 6
// speedup vs baseline: 3.6256x; 1.1672x over previous
#include <cuda_runtime.h>
#include <cuda_bf16.h>
#include <cuda_fp16.h>
#include <stdint.h>

#define NPTS 1024
#define NTH  512
#define THR2 0.09f

typedef unsigned long long u64;

// ---------------- smem byte-offset map (GCN kernel) ----------------
// B fragments (fp16 single): [c(2)][k16(64)][nt(4)][lane(32)][8B: b0,b1] = 128KB
#define OFF_B    0
#define OFF_PX   131072
#define OFF_PY   135168
#define OFF_DINV 139264
#define OFF_SX   143360
#define OFF_SY   147456
#define OFF_W2   151552   // 16KB
#define OFF_W1   167936   // 512B
#define OFF_B1   168448
#define OFF_B2   168704
#define OFF_CS   168960
#define OFF_GV   169216
#define SMEM_GCN 169472

__device__ float g_gi[128 * 384];

// ---------------- helpers ----------------
__device__ __forceinline__ u64 pack2f(float a, float b) {
    u64 r; asm("mov.b64 %0, {%1, %2};" : "=l"(r) : "f"(a), "f"(b)); return r;
}
__device__ __forceinline__ u64 ld2(const float* p) {
    float2 v = *(const float2*)p;
    return pack2f(v.x, v.y);
}
#define FMA2(acc, a, b) asm("fma.rn.f32x2 %0, %1, %2, %0;" : "+l"(acc) : "l"(a), "l"(b))
__device__ __forceinline__ u64 add2(u64 a, u64 b) {
    u64 r; asm("add.rn.f32x2 %0, %1, %2;" : "=l"(r) : "l"(a), "l"(b)); return r;
}
__device__ __forceinline__ u64 fma2v(u64 a, u64 b, u64 c) {
    u64 r; asm("fma.rn.f32x2 %0, %1, %2, %3;" : "=l"(r) : "l"(a), "l"(b), "l"(c)); return r;
}
// mask pair: fp16x2 {adj(i,j0), adj(i,j1)}; u = dx^2 + dy^2 - thr2, neighbor <=> sign(u)
__device__ __forceinline__ uint32_t maskpair(u64 px2, u64 py2, u64 nx2, u64 ny2,
                                             u64 one2, u64 nthr2) {
    u64 dx, dy, u;
    asm("fma.rn.f32x2 %0, %1, %2, %3;" : "=l"(dx) : "l"(px2), "l"(one2), "l"(nx2));
    asm("fma.rn.f32x2 %0, %1, %2, %3;" : "=l"(dy) : "l"(py2), "l"(one2), "l"(ny2));
    asm("fma.rn.f32x2 %0, %1, %1, %2;" : "=l"(u)  : "l"(dy), "l"(nthr2));
    asm("fma.rn.f32x2 %0, %1, %1, %0;" : "+l"(u)  : "l"(dx));
    uint32_t lo, hi, m;
    asm("mov.b64 {%0, %1}, %2;" : "=r"(lo), "=r"(hi) : "l"(u));
    asm("prmt.b32 %0, %1, %2, 0xFFBB;" : "=r"(m) : "r"(lo), "r"(hi));
    return m & 0x3C003C00u;   // fp16 1.0 per half where neighbor
}
__device__ __forceinline__ void mma_f16(float* d, uint32_t a0, uint32_t a1,
                                        uint32_t a2, uint32_t a3,
                                        uint32_t b0, uint32_t b1) {
    asm("mma.sync.aligned.m16n8k16.row.col.f32.f16.f16.f32 "
        "{%0,%1,%2,%3}, {%4,%5,%6,%7}, {%8,%9}, {%0,%1,%2,%3};"
        : "+f"(d[0]), "+f"(d[1]), "+f"(d[2]), "+f"(d[3])
        : "r"(a0), "r"(a1), "r"(a2), "r"(a3), "r"(b0), "r"(b1));
}

// ---------------- GCN kernel ----------------
__global__ void __launch_bounds__(NTH, 1) gcn_kernel(
    const float* __restrict__ points,
    const float* __restrict__ W1, const float* __restrict__ b1,
    const float* __restrict__ W2, const float* __restrict__ b2,
    const float* __restrict__ Wg, const float* __restrict__ bg,
    const float* __restrict__ Wih, const float* __restrict__ bih)
{
    extern __shared__ char smem[];
    float* px   = (float*)(smem + OFF_PX);
    float* py   = (float*)(smem + OFF_PY);
    float* dinv = (float*)(smem + OFF_DINV);
    float* sx   = (float*)(smem + OFF_SX);
    float* sy   = (float*)(smem + OFF_SY);
    float* w2s  = (float*)(smem + OFF_W2);
    float* w1s  = (float*)(smem + OFF_W1);
    float* b1s  = (float*)(smem + OFF_B1);
    float* b2s  = (float*)(smem + OFF_B2);
    float* colsum = (float*)(smem + OFF_CS);
    float* gcnv   = (float*)(smem + OFF_GV);

    const int g    = blockIdx.x;
    const int tid  = threadIdx.x;
    const int lane = tid & 31;
    const int warp = tid >> 5;

    // ---- load points + weights ----
    const float* pts = points + (size_t)g * NPTS * 2;
    for (int j = tid; j < NPTS; j += NTH) {
        float2 p = ((const float2*)pts)[j];
        px[j] = p.x; py[j] = p.y;
    }
    for (int i = tid; i < 128; i += NTH)  w1s[i] = W1[i];
    for (int i = tid; i < 4096; i += NTH) w2s[i] = W2[i];
    if (tid < 64) { b1s[tid] = b1[tid]; b2s[tid] = b2[tid]; colsum[tid] = 0.f; }
    __syncthreads();

    const u64 one2  = pack2f(1.f, 1.f);
    const u64 nthr2 = pack2f(-THR2, -THR2);
    const u64* pxp = (const u64*)px;
    const u64* pyp = (const u64*)py;

    // ---- degree pass (packed f32x2, sign-bit count) ----
    for (int ig = 0; ig < 2; ig++) {
        int i = tid + ig * NTH;
        u64 nxi = pack2f(-px[i], -px[i]);
        u64 nyi = pack2f(-py[i], -py[i]);
        uint32_t cnt = 0;
        #pragma unroll 4
        for (int jp = 0; jp < NPTS / 2; jp++) {
            u64 dx2 = add2(pxp[jp], nxi);
            u64 dy2 = add2(pyp[jp], nyi);
            u64 u = fma2v(dy2, dy2, nthr2);
            FMA2(u, dx2, dx2);
            cnt += ((uint32_t)u >> 31) + ((uint32_t)(u >> 32) >> 31);
        }
        dinv[i] = rsqrtf((float)cnt);
    }
    __syncthreads();

    // ---- s pass: s = An @ pts (packed f32x2, sign-mask select of dinv) ----
    const u64* dvp = (const u64*)dinv;
    for (int ig = 0; ig < 2; ig++) {
        int i = tid + ig * NTH;
        u64 nxi = pack2f(-px[i], -px[i]);
        u64 nyi = pack2f(-py[i], -py[i]);
        u64 ax2 = 0ULL, ay2 = 0ULL;
        #pragma unroll 4
        for (int jp = 0; jp < NPTS / 2; jp++) {
            u64 px2 = pxp[jp], py2 = pyp[jp];
            u64 dx2 = add2(px2, nxi);
            u64 dy2 = add2(py2, nyi);
            u64 u = fma2v(dy2, dy2, nthr2);
            FMA2(u, dx2, dx2);
            uint32_t mlo = (uint32_t)(((int32_t)(uint32_t)u) >> 31);
            uint32_t mhi = (uint32_t)(((int32_t)(uint32_t)(u >> 32)) >> 31);
            u64 dv = dvp[jp];
            u64 m2 = (u64)((uint32_t)dv & mlo) | (((u64)((uint32_t)(dv >> 32) & mhi)) << 32);
            FMA2(ax2, m2, px2);
            FMA2(ay2, m2, py2);
        }
        float axl, axh, ayl, ayh;
        asm("mov.b64 {%0, %1}, %2;" : "=f"(axl), "=f"(axh) : "l"(ax2));
        asm("mov.b64 {%0, %1}, %2;" : "=f"(ayl), "=f"(ayh) : "l"(ay2));
        float di = dinv[i];
        sx[i] = di * (axl + axh);
        sy[i] = di * (ayl + ayh);
    }
    __syncthreads();

    // =================== MMA phase (mma.sync f16 single-pass) ===================
    const int R  = warp * 64;
    const int l4 = lane >> 4 ? 0 : 0;  // placeholder (unused)
    const int g4 = lane >> 2;

    float nxr[8], nyr[8];
    #pragma unroll
    for (int q = 0; q < 8; q++) {
        int i = R + (q >> 1) * 16 + g4 + (q & 1) * 8;
        nxr[q] = -px[i]; nyr[q] = -py[i];
    }

    // ---- single B-build: all 64 cols, fp16, dinv folded into x1 ----
    for (int jj = tid; jj < NPTS; jj += NTH) {
        float s0 = sx[jj], s1 = sy[jj], dj = dinv[jj];
        u64 x1p[32];
        #pragma unroll
        for (int k2 = 0; k2 < 32; k2++) {
            float v0 = fmaxf(fmaf(s0, w1s[4*k2],   fmaf(s1, w1s[4*k2+1], b1s[2*k2])),   0.f) * dj;
            float v1 = fmaxf(fmaf(s0, w1s[4*k2+2], fmaf(s1, w1s[4*k2+3], b1s[2*k2+1])), 0.f) * dj;
            x1p[k2] = pack2f(v0, v1);
        }
        int k16 = jj >> 4, r = jj & 15;
        // base byte offset within (k16, nt, lane) 8B cell for row r
        int bj = OFF_B + k16 * 1024 + ((r & 7) >> 1) * 8 + (r >> 3) * 4 + (r & 1) * 2;
        #pragma unroll 1
        for (int mm = 0; mm < 64; mm++) {
            const u64* w2p = (const u64*)(w2s + mm * 64);
            u64 a2 = 0ULL;
            #pragma unroll
            for (int k2 = 0; k2 < 32; k2++) FMA2(a2, x1p[k2], w2p[k2]);
            float al, ah;
            asm("mov.b64 {%0, %1}, %2;" : "=f"(al), "=f"(ah) : "l"(a2));
            float w = al + ah;
            // c = mm>>5 chunk, nt = (mm>>3)&3, n-in-tile = mm&7 -> lane = ((mm&7)<<2) | ((r&7)>>1)
            int off = bj + (mm >> 5) * 65536 + ((mm >> 3) & 3) * 256 + (mm & 7) * 32;
            *(__half*)(smem + off) = __float2half(w);
        }
    }
    __syncthreads();

    for (int c = 0; c < 2; c++) {
        // ---- k-loop: A frags in registers, single f16 mma accumulate ----
        float acc[4][4][4] = {};
        #pragma unroll 1
        for (int k16 = 0; k16 < 64; k16++) {
            int jA = k16 * 16 + (lane & 3) * 2;
            u64 pax = ld2(px + jA),     pay = ld2(py + jA);
            u64 pbx = ld2(px + jA + 8), pby = ld2(py + jA + 8);

            uint32_t A[4][4];
            #pragma unroll
            for (int mt = 0; mt < 4; mt++) {
                u64 nx0 = pack2f(nxr[mt*2],   nxr[mt*2]);
                u64 ny0 = pack2f(nyr[mt*2],   nyr[mt*2]);
                u64 nx1 = pack2f(nxr[mt*2+1], nxr[mt*2+1]);
                u64 ny1 = pack2f(nyr[mt*2+1], nyr[mt*2+1]);
                A[mt][0] = maskpair(pax, pay, nx0, ny0, one2, nthr2);
                A[mt][1] = maskpair(pax, pay, nx1, ny1, one2, nthr2);
                A[mt][2] = maskpair(pbx, pby, nx0, ny0, one2, nthr2);
                A[mt][3] = maskpair(pbx, pby, nx1, ny1, one2, nthr2);
            }
            #pragma unroll
            for (int nt = 0; nt < 4; nt++) {
                uint2 bv = *(const uint2*)(smem + OFF_B + c * 65536
                                           + k16 * 1024 + nt * 256 + lane * 8);
                #pragma unroll
                for (int mt = 0; mt < 4; mt++)
                    mma_f16(acc[mt][nt], A[mt][0], A[mt][1], A[mt][2], A[mt][3], bv.x, bv.y);
            }
        }

        // ---- epilogue: relu(dinv_i*acc + b2), column sums ----
        float cs[4][2] = {};
        #pragma unroll
        for (int mt = 0; mt < 4; mt++) {
            float di0 = dinv[R + mt*16 + g4];
            float di1 = dinv[R + mt*16 + g4 + 8];
            #pragma unroll
            for (int nt = 0; nt < 4; nt++) {
                int col0 = c * 32 + nt * 8 + (lane & 3) * 2;
                float b20 = b2s[col0], b21 = b2s[col0 + 1];
                cs[nt][0] += fmaxf(fmaf(di0, acc[mt][nt][0], b20), 0.f);
                cs[nt][1] += fmaxf(fmaf(di0, acc[mt][nt][1], b21), 0.f);
                cs[nt][0] += fmaxf(fmaf(di1, acc[mt][nt][2], b20), 0.f);
                cs[nt][1] += fmaxf(fmaf(di1, acc[mt][nt][3], b21), 0.f);
            }
        }
        #pragma unroll
        for (int nt = 0; nt < 4; nt++)
            #pragma unroll
            for (int p = 0; p < 2; p++) {
                float v = cs[nt][p];
                v += __shfl_xor_sync(0xffffffffu, v, 4);
                v += __shfl_xor_sync(0xffffffffu, v, 8);
                v += __shfl_xor_sync(0xffffffffu, v, 16);
                if (lane < 4)
                    atomicAdd(&colsum[c * 32 + nt * 8 + lane * 2 + p], v);
            }
    }
    __syncthreads();

    // ---- head: gcn = Wg @ mean + bg ; gi = Wih @ gcn + bih ----
    if (tid < 64) {
        float acc = bg[tid];
        const float inv = 1.0f / 1024.f;
        #pragma unroll 8
        for (int m = 0; m < 64; m++)
            acc = fmaf(colsum[m] * inv, Wg[tid * 64 + m], acc);
        gcnv[tid] = acc;
    }
    __syncthreads();
    if (tid < 384) {
        float acc = bih[tid];
        const float* wr = Wih + tid * 64;
        #pragma unroll 8
        for (int c2 = 0; c2 < 64; c2++)
            acc = fmaf(wr[c2], gcnv[c2], acc);
        g_gi[g * 384 + tid] = acc;
    }
}

// ---------------- GRU kernel: Whh in registers, 4-way split accumulators ----------------
__global__ void __launch_bounds__(384, 1) gru_kernel(
    const float* __restrict__ Whh, const float* __restrict__ bhh,
    const float* __restrict__ Wf,  const float* __restrict__ bf,
    float* __restrict__ out)
{
    __shared__ __align__(16) float h[128];
    __shared__ float gh_s[384];
    __shared__ float gi_s[384];
    __shared__ float hsum_s[128];

    const int b   = blockIdx.x;
    const int tid = threadIdx.x;

    u64 wreg[64];
    const u64* wg = (const u64*)Whh;
    #pragma unroll
    for (int c2 = 0; c2 < 64; c2++) wreg[c2] = wg[tid * 64 + c2];

    if (tid < 128) h[tid] = 0.f;
    const float bhh_r = bhh[tid];
    const float* gib = g_gi + (size_t)b * 32 * 384;
    float gi_cur = gib[tid];
    float hsum = 0.f;
    __syncthreads();

    for (int t = 0; t < 32; t++) {
        float gi_nxt = (t < 31) ? gib[(t + 1) * 384 + tid] : 0.f;
        gi_s[tid] = gi_cur;

        // gh[tid] = Whh[tid].h + bhh[tid], 4 independent FMA2 chains
        u64 a0 = pack2f(bhh_r, 0.f), a1 = 0ULL, a2 = 0ULL, a3 = 0ULL;
        const double2* hv4 = (const double2*)h;
        #pragma unroll
        for (int c8 = 0; c8 < 16; c8++) {
            double2 hva = hv4[2*c8];
            double2 hvb = hv4[2*c8 + 1];
            FMA2(a0, wreg[4*c8],     __double_as_longlong(hva.x));
            FMA2(a1, wreg[4*c8 + 1], __double_as_longlong(hva.y));
            FMA2(a2, wreg[4*c8 + 2], __double_as_longlong(hvb.x));
            FMA2(a3, wreg[4*c8 + 3], __double_as_longlong(hvb.y));
        }
        u64 s01 = add2(a0, a1), s23 = add2(a2, a3);
        u64 stot = add2(s01, s23);
        float alo, ahi;
        asm("mov.b64 {%0, %1}, %2;" : "=f"(alo), "=f"(ahi) : "l"(stot));
        gh_s[tid] = alo + ahi;
        __syncthreads();

        if (tid < 128) {
            float rg = 1.f / (1.f + __expf(-(gi_s[tid]       + gh_s[tid])));
            float zg = 1.f / (1.f + __expf(-(gi_s[128 + tid] + gh_s[128 + tid])));
            float un = gi_s[256 + tid] + rg * gh_s[256 + tid];
            float e  = __expf(-2.f * un);
            float ng = fmaf(2.f, __frcp_rn(1.f + e), -1.f);
            float hn = (1.f - zg) * ng + zg * h[tid];
            h[tid] = hn;
            hsum += hn;
        }
        __syncthreads();
        gi_cur = gi_nxt;
    }

    if (tid < 128) hsum_s[tid] = hsum;
    __syncthreads();
    if (tid < 2) {
        float acc = bf[tid];
        const float inv = 1.0f / 32.f;
        #pragma unroll 8
        for (int c = 0; c < 128; c++)
            acc = fmaf(Wf[tid * 128 + c], hsum_s[c] * inv, acc);
        out[b * 2 + tid] = acc;
    }
}

extern "C" void kernel_launch(void* const* d_in, const int* in_sizes, int n_in,
                              void* d_out, int out_size) {
    const float* points = (const float*)d_in[0];
    const float* W1  = (const float*)d_in[1];
    const float* b1  = (const float*)d_in[2];
    const float* W2  = (const float*)d_in[3];
    const float* b2  = (const float*)d_in[4];
    const float* Wg  = (const float*)d_in[5];
    const float* bg  = (const float*)d_in[6];
    const float* Wih = (const float*)d_in[7];
    const float* Whh = (const float*)d_in[8];
    const float* bih = (const float*)d_in[9];
    const float* bhh = (const float*)d_in[10];
    const float* Wf  = (const float*)d_in[11];
    const float* bf  = (const float*)d_in[12];
    float* out = (float*)d_out;

    cudaFuncSetAttribute(gcn_kernel, cudaFuncAttributeMaxDynamicSharedMemorySize, SMEM_GCN);

    gcn_kernel<<<128, NTH, SMEM_GCN>>>(points, W1, b1, W2, b2, Wg, bg, Wih, bih);
    gru_kernel<<<4, 384>>>(Whh, bhh, Wf, bf, out);
}